// round 14
// baseline (speedup 1.0000x reference)
#include <cuda_runtime.h>
#include <cuda_fp16.h>
#include <cstdint>

#define TSEQ 200
#define PSTEPS 50
#define BATCHN 32768
#define GSAMP 16
#define NCTA (BATCHN / GSAMP)   // 2048 single-warp CTAs
#define H05 0x38003800u         // (0.5, 0.5) f16x2
#define HONE 0x00003C00u        // (1.0, 0.0) f16x2

// ---------------- helpers ----------------
__device__ __forceinline__ uint32_t packh(float a, float b) {  // (f16(a), f16(b))
    uint32_t r;
    asm("{.reg .b16 x,y; cvt.rn.f16.f32 x, %1; cvt.rn.f16.f32 y, %2; mov.b32 %0, {x,y};}"
        : "=r"(r) : "f"(a), "f"(b));
    return r;
}
__device__ __forceinline__ uint32_t tanh2(uint32_t x) {
    uint32_t r; asm("tanh.approx.f16x2 %0, %1;" : "=r"(r) : "r"(x)); return r;
}
__device__ __forceinline__ uint32_t mul2(uint32_t a, uint32_t b) {
    uint32_t r; asm("mul.rn.f16x2 %0, %1, %2;" : "=r"(r) : "r"(a), "r"(b)); return r;
}
__device__ __forceinline__ uint32_t fma2h(uint32_t a, uint32_t b, uint32_t c) {
    uint32_t r; asm("fma.rn.f16x2 %0, %1, %2, %3;" : "=r"(r) : "r"(a), "r"(b), "r"(c)); return r;
}
__device__ __forceinline__ uint32_t sigm2(uint32_t g) {   // 0.5*tanh(0.5g)+0.5
    return fma2h(H05, tanh2(mul2(g, H05)), H05);
}
__device__ __forceinline__ uint32_t prmt(uint32_t a, uint32_t b, uint32_t c) {
    uint32_t r; asm("prmt.b32 %0, %1, %2, %3;" : "=r"(r) : "r"(a), "r"(b), "r"(c)); return r;
}
// f16-accumulator gate MMAs
__device__ __forceinline__ void mma16816h(uint32_t* d, const uint32_t* a, const uint32_t* b) {
    asm volatile("mma.sync.aligned.m16n8k16.row.col.f16.f16.f16.f16 "
                 "{%0,%1}, {%2,%3,%4,%5}, {%6,%7}, {%0,%1};"
                 : "+r"(d[0]), "+r"(d[1])
                 : "r"(a[0]), "r"(a[1]), "r"(a[2]), "r"(a[3]), "r"(b[0]), "r"(b[1]));
}
__device__ __forceinline__ void mma1688h(uint32_t* d, const uint32_t* a, uint32_t b) {
    asm volatile("mma.sync.aligned.m16n8k8.row.col.f16.f16.f16.f16 "
                 "{%0,%1}, {%2,%3}, {%4}, {%0,%1};"
                 : "+r"(d[0]), "+r"(d[1])
                 : "r"(a[0]), "r"(a[1]), "r"(b));
}
// f32-accumulator MMAs (pred output path only — error there is undamped)
__device__ __forceinline__ void mma16816(float* d, const uint32_t* a, const uint32_t* b) {
    asm volatile("mma.sync.aligned.m16n8k16.row.col.f32.f16.f16.f32 "
                 "{%0,%1,%2,%3}, {%4,%5,%6,%7}, {%8,%9}, {%0,%1,%2,%3};"
                 : "+f"(d[0]), "+f"(d[1]), "+f"(d[2]), "+f"(d[3])
                 : "r"(a[0]), "r"(a[1]), "r"(a[2]), "r"(a[3]), "r"(b[0]), "r"(b[1]));
}
__device__ __forceinline__ void mma1688(float* d, const uint32_t* a, uint32_t b) {
    asm volatile("mma.sync.aligned.m16n8k8.row.col.f32.f16.f16.f32 "
                 "{%0,%1,%2,%3}, {%4,%5}, {%6}, {%0,%1,%2,%3};"
                 : "+f"(d[0]), "+f"(d[1]), "+f"(d[2]), "+f"(d[3])
                 : "r"(a[0]), "r"(a[1]), "r"(b));
}

// Column map: tile t (0..15), col c (0..7) ->
//   unit u = 2*(c>>1) + ((t>>1)&1) + 8*(t>>2)
//   even t: (i | f) by c&1 ; odd t: (g | o)
// so lane j's tile-pair s (=t>>1) holds the full (i,f,g,o) quad of unit
// u(s,j) = 2j + (s&1) + 8*(s>>1)  — exactly the units its A-frag needs.
__device__ __forceinline__ int prow16(int t, int c) {
    int u   = 2 * (c >> 1) + ((t >> 1) & 1) + 8 * (t >> 2);
    int dj  = c & 1;
    int blk = (t & 1) ? (dj ? 3 : 2) : (dj ? 1 : 0);   // i,f,g,o row blocks
    return blk * 32 + u;
}

__global__ void __launch_bounds__(32, 14) lstm_hmma_kernel(
    const float* __restrict__ hist,
    const float* __restrict__ Wih,
    const float* __restrict__ Whh,
    const float* __restrict__ bih,
    const float* __restrict__ bhh,
    const float* __restrict__ Wpred,
    const float* __restrict__ bpred,
    float* __restrict__ out)
{
    const int lane = threadIdx.x;
    const int j    = lane & 3;          // col-pair / k-pair index
    const int nsub = lane >> 2;         // B col (0..7), also A row r
    const int r    = nsub;
    const int k0   = 2 * j;
    const int S0   = blockIdx.x * GSAMP;

    uint32_t Bh[16][2][2], Bx[16];      // all 16 gate n-tiles (this warp owns N=128)

    // ---- build encoder B frags ----
#pragma unroll
    for (int t = 0; t < 16; t++) {
        int pr = prow16(t, nsub);
#pragma unroll
        for (int c = 0; c < 2; c++) {
            int kb = c * 16;
            Bh[t][c][0] = packh(Whh[pr * 32 + kb + k0],     Whh[pr * 32 + kb + k0 + 1]);
            Bh[t][c][1] = packh(Whh[pr * 32 + kb + k0 + 8], Whh[pr * 32 + kb + k0 + 9]);
        }
        // x-chunk (k8): rows 0-3 = Wih, row 4 = bias (A k4 = ones)
        float v0 = 0.0f, v1 = 0.0f;
        if (j == 0)      { v0 = Wih[pr * 4 + 0]; v1 = Wih[pr * 4 + 1]; }
        else if (j == 1) { v0 = Wih[pr * 4 + 2]; v1 = Wih[pr * 4 + 3]; }
        else if (j == 2) { v0 = bih[pr] + bhh[pr]; }
        Bx[t] = packh(v0, v1);
    }

    // ---- A state: h lives in registers forever ----
    uint32_t Ah0[4] = {0u, 0u, 0u, 0u};
    uint32_t Ah1[4] = {0u, 0u, 0u, 0u};
    uint32_t Ax[2];
    {
        float2 a0 = make_float2(0.f, 0.f), a1 = make_float2(0.f, 0.f);
        if (j < 2) {
            a0 = *(const float2*)(hist + ((size_t)(S0 + r)     * TSEQ) * 4 + k0);
            a1 = *(const float2*)(hist + ((size_t)(S0 + r + 8) * TSEQ) * 4 + k0);
        }
        Ax[0] = (j == 2) ? HONE : packh(a0.x, a0.y);
        Ax[1] = (j == 2) ? HONE : packh(a1.x, a1.y);
    }

    uint32_t cst2[8];                   // c state: 8 units x f16x2(rows r, r+8)
#pragma unroll
    for (int s = 0; s < 8; s++) cst2[s] = 0u;

    // =================== encoder: 200 steps ===================
    for (int t = 0; t < TSEQ; t++) {
        // prefetch next x while MMAs run
        float2 xr0 = make_float2(0.f, 0.f), xr1 = make_float2(0.f, 0.f);
        const bool more = (t + 1 < TSEQ);
        if (more && j < 2) {
            xr0 = *(const float2*)(hist + ((size_t)(S0 + r)     * TSEQ + t + 1) * 4 + k0);
            xr1 = *(const float2*)(hist + ((size_t)(S0 + r + 8) * TSEQ + t + 1) * 4 + k0);
        }

        uint32_t h2[8];
#pragma unroll
        for (int s = 0; s < 8; s++) {
            uint32_t d0[2] = {0u, 0u}, d1[2] = {0u, 0u};
            mma16816h(d0, Ah0, Bh[2 * s][0]);
            mma16816h(d0, Ah1, Bh[2 * s][1]);
            mma1688h (d0, Ax,  Bx[2 * s]);
            mma16816h(d1, Ah0, Bh[2 * s + 1][0]);
            mma16816h(d1, Ah1, Bh[2 * s + 1][1]);
            mma1688h (d1, Ax,  Bx[2 * s + 1]);
            uint32_t i2 = prmt(d0[0], d0[1], 0x5410u);
            uint32_t f2 = prmt(d0[0], d0[1], 0x7632u);
            uint32_t g2 = prmt(d1[0], d1[1], 0x5410u);
            uint32_t o2 = prmt(d1[0], d1[1], 0x7632u);
            uint32_t itg = mul2(sigm2(i2), tanh2(g2));
            uint32_t cn2 = fma2h(sigm2(f2), cst2[s], itg);
            cst2[s] = cn2;
            h2[s] = mul2(sigm2(o2), tanh2(cn2));
        }
        // rebuild A frags from own h (pure register transpose)
        Ah0[0] = prmt(h2[0], h2[1], 0x5410u);  Ah0[1] = prmt(h2[0], h2[1], 0x7632u);
        Ah0[2] = prmt(h2[2], h2[3], 0x5410u);  Ah0[3] = prmt(h2[2], h2[3], 0x7632u);
        Ah1[0] = prmt(h2[4], h2[5], 0x5410u);  Ah1[1] = prmt(h2[4], h2[5], 0x7632u);
        Ah1[2] = prmt(h2[6], h2[7], 0x5410u);  Ah1[3] = prmt(h2[6], h2[7], 0x7632u);
        if (more) {
            Ax[0] = (j == 2) ? HONE : packh(xr0.x, xr0.y);
            Ax[1] = (j == 2) ? HONE : packh(xr1.x, xr1.y);
        }
    }

    // =================== decode boundary: fused weights ===================
#pragma unroll
    for (int t = 0; t < 16; t++) {
        int pr = prow16(t, nsub);
#pragma unroll
        for (int c = 0; c < 2; c++) {
            int kb = c * 16;
            float wv[4];
#pragma unroll
            for (int q = 0; q < 4; q++) {
                int kk = kb + ((q < 2) ? k0 : k0 + 8) + (q & 1);
                float v = Whh[pr * 32 + kk];
#pragma unroll
                for (int d = 0; d < 4; d++)
                    v += Wih[pr * 4 + d] * Wpred[d * 32 + kk];
                wv[q] = v;
            }
            Bh[t][c][0] = packh(wv[0], wv[1]);
            Bh[t][c][1] = packh(wv[2], wv[3]);
        }
        float bd = 0.0f;
        if (j == 2) {
            bd = bih[pr] + bhh[pr];
#pragma unroll
            for (int d = 0; d < 4; d++) bd += Wih[pr * 4 + d] * bpred[d];
        }
        Bx[t] = packh(bd, 0.0f);
    }
    // pred tile: cols = pred dims 0-3 (4-7 zero), f32 accum path
    uint32_t Ph[2][2], Px;
    {
        int d = nsub;
        bool ok = (d < 4);
#pragma unroll
        for (int c = 0; c < 2; c++) {
            int kb = c * 16;
            Ph[c][0] = packh(ok ? Wpred[d * 32 + kb + k0]     : 0.0f,
                             ok ? Wpred[d * 32 + kb + k0 + 1] : 0.0f);
            Ph[c][1] = packh(ok ? Wpred[d * 32 + kb + k0 + 8] : 0.0f,
                             ok ? Wpred[d * 32 + kb + k0 + 9] : 0.0f);
        }
        Px = packh((j == 2 && ok) ? bpred[d] : 0.0f, 0.0f);
    }
    // decode x-chunk A: only the ones column (bias) is live
    Ax[0] = (j == 2) ? HONE : 0u;
    Ax[1] = Ax[0];

    // =================== decode: 50 steps ===================
    for (int ps = 0; ps < PSTEPS; ps++) {
        // prediction (f32 accum, direct to output)
        float dp[4] = {0.0f, 0.0f, 0.0f, 0.0f};
        mma16816(dp, Ah0, Ph[0]);
        mma16816(dp, Ah1, Ph[1]);
        mma1688 (dp, Ax, Px);
        if (j < 2) {
            float2* o0 = (float2*)(out + (size_t)(S0 + r)     * (PSTEPS * 4) + ps * 4 + k0);
            float2* o1 = (float2*)(out + (size_t)(S0 + r + 8) * (PSTEPS * 4) + ps * 4 + k0);
            *o0 = make_float2(dp[0], dp[1]);
            *o1 = make_float2(dp[2], dp[3]);
        }

        uint32_t h2[8];
#pragma unroll
        for (int s = 0; s < 8; s++) {
            uint32_t d0[2] = {0u, 0u}, d1[2] = {0u, 0u};
            mma16816h(d0, Ah0, Bh[2 * s][0]);
            mma16816h(d0, Ah1, Bh[2 * s][1]);
            mma1688h (d0, Ax,  Bx[2 * s]);
            mma16816h(d1, Ah0, Bh[2 * s + 1][0]);
            mma16816h(d1, Ah1, Bh[2 * s + 1][1]);
            mma1688h (d1, Ax,  Bx[2 * s + 1]);
            uint32_t i2 = prmt(d0[0], d0[1], 0x5410u);
            uint32_t g2 = prmt(d1[0], d1[1], 0x5410u);
            uint32_t o2 = prmt(d1[0], d1[1], 0x7632u);
            uint32_t cn2 = mul2(sigm2(i2), tanh2(g2));   // c resets each step
            h2[s] = mul2(sigm2(o2), tanh2(cn2));
        }
        Ah0[0] = prmt(h2[0], h2[1], 0x5410u);  Ah0[1] = prmt(h2[0], h2[1], 0x7632u);
        Ah0[2] = prmt(h2[2], h2[3], 0x5410u);  Ah0[3] = prmt(h2[2], h2[3], 0x7632u);
        Ah1[0] = prmt(h2[4], h2[5], 0x5410u);  Ah1[1] = prmt(h2[4], h2[5], 0x7632u);
        Ah1[2] = prmt(h2[6], h2[7], 0x5410u);  Ah1[3] = prmt(h2[6], h2[7], 0x7632u);
    }
}

extern "C" void kernel_launch(void* const* d_in, const int* in_sizes, int n_in,
                              void* d_out, int out_size) {
    const float* hist  = (const float*)d_in[0];
    const float* Wih   = (const float*)d_in[1];
    const float* Whh   = (const float*)d_in[2];
    const float* bih   = (const float*)d_in[3];
    const float* bhh   = (const float*)d_in[4];
    const float* Wpred = (const float*)d_in[5];
    const float* bpred = (const float*)d_in[6];
    lstm_hmma_kernel<<<NCTA, 32>>>(hist, Wih, Whh, bih, bhh, Wpred, bpred,
                                   (float*)d_out);
}

// round 15
// speedup vs baseline: 1.2565x; 1.2565x over previous
#include <cuda_runtime.h>
#include <cuda_fp16.h>
#include <cstdint>

#define TSEQ 200
#define PSTEPS 50
#define BATCHN 32768
#define GSAMP 16
#define NCTA (BATCHN / GSAMP)   // 2048
#define XH_STR 40               // f16 elems per row (80B, 16B aligned, conflict-free ldsm)
#define XX_STR 8                // 16B rows (k8 x-chunk)
#define H05 0x38003800u         // (0.5, 0.5) f16x2

// ---------------- helpers ----------------
__device__ __forceinline__ uint32_t s2u(const void* p) {
    uint32_t a;
    asm("{ .reg .u64 t; cvta.to.shared.u64 t, %1; cvt.u32.u64 %0, t; }" : "=r"(a) : "l"(p));
    return a;
}
__device__ __forceinline__ uint32_t packh(float a, float b) {  // (f16(a), f16(b))
    uint32_t r;
    asm("{.reg .b16 x,y; cvt.rn.f16.f32 x, %1; cvt.rn.f16.f32 y, %2; mov.b32 %0, {x,y};}"
        : "=r"(r) : "f"(a), "f"(b));
    return r;
}
__device__ __forceinline__ uint32_t tanh2(uint32_t x) {
    uint32_t r; asm("tanh.approx.f16x2 %0, %1;" : "=r"(r) : "r"(x)); return r;
}
__device__ __forceinline__ uint32_t mul2(uint32_t a, uint32_t b) {
    uint32_t r; asm("mul.rn.f16x2 %0, %1, %2;" : "=r"(r) : "r"(a), "r"(b)); return r;
}
__device__ __forceinline__ uint32_t fma2h(uint32_t a, uint32_t b, uint32_t c) {
    uint32_t r; asm("fma.rn.f16x2 %0, %1, %2, %3;" : "=r"(r) : "r"(a), "r"(b), "r"(c)); return r;
}
// gates arrive pre-scaled by 0.5 (folded into weights): sigm = 0.5*tanh(g') + 0.5
__device__ __forceinline__ uint32_t sigm2f(uint32_t gpre) {
    return fma2h(H05, tanh2(gpre), H05);
}
__device__ __forceinline__ uint32_t prmt(uint32_t a, uint32_t b, uint32_t c) {
    uint32_t r; asm("prmt.b32 %0, %1, %2, %3;" : "=r"(r) : "r"(a), "r"(b), "r"(c)); return r;
}
// f16-accumulator gate MMAs
__device__ __forceinline__ void mma16816h(uint32_t* d, const uint32_t* a, const uint32_t* b) {
    asm volatile("mma.sync.aligned.m16n8k16.row.col.f16.f16.f16.f16 "
                 "{%0,%1}, {%2,%3,%4,%5}, {%6,%7}, {%0,%1};"
                 : "+r"(d[0]), "+r"(d[1])
                 : "r"(a[0]), "r"(a[1]), "r"(a[2]), "r"(a[3]), "r"(b[0]), "r"(b[1]));
}
__device__ __forceinline__ void mma1688h(uint32_t* d, const uint32_t* a, uint32_t b) {
    asm volatile("mma.sync.aligned.m16n8k8.row.col.f16.f16.f16.f16 "
                 "{%0,%1}, {%2,%3}, {%4}, {%0,%1};"
                 : "+r"(d[0]), "+r"(d[1])
                 : "r"(a[0]), "r"(a[1]), "r"(b));
}
// f32-accumulator MMA (pred output path only — error there is undamped)
__device__ __forceinline__ void mma16816(float* d, const uint32_t* a, const uint32_t* b) {
    asm volatile("mma.sync.aligned.m16n8k16.row.col.f32.f16.f16.f32 "
                 "{%0,%1,%2,%3}, {%4,%5,%6,%7}, {%8,%9}, {%0,%1,%2,%3};"
                 : "+f"(d[0]), "+f"(d[1]), "+f"(d[2]), "+f"(d[3])
                 : "r"(a[0]), "r"(a[1]), "r"(a[2]), "r"(a[3]), "r"(b[0]), "r"(b[1]));
}
__device__ __forceinline__ void ldsm4(uint32_t* r, uint32_t addr) {
    asm volatile("ldmatrix.sync.aligned.m8n8.x4.shared.b16 {%0,%1,%2,%3}, [%4];"
                 : "=r"(r[0]), "=r"(r[1]), "=r"(r[2]), "=r"(r[3]) : "r"(addr));
}
__device__ __forceinline__ void ldsm2(uint32_t* r, uint32_t addr) {
    asm volatile("ldmatrix.sync.aligned.m8n8.x2.shared.b16 {%0,%1}, [%2];"
                 : "=r"(r[0]), "=r"(r[1]) : "r"(addr));
}
__device__ __forceinline__ void sts_halves(uint32_t h2, uint32_t alo, uint32_t ahi) {
    asm volatile("{.reg .b16 lo,hi; mov.b32 {lo,hi}, %0; "
                 "st.shared.b16 [%1], lo; st.shared.b16 [%2], hi;}"
                 :: "r"(h2), "r"(alo), "r"(ahi));
}

// Shuffle-free gate-column map: lane j's four gate tiles hold complete
// (i,f,g,o) for units 8w+j and 8w+j+4, rows r and r+8.
__device__ __forceinline__ int prow(int col) {
    int t  = (col >> 3) & 3;
    int jc = (col >> 1) & 3;
    int dj = col & 1;
    int u  = ((col >> 5) << 3) + jc + ((t >> 1) << 2);
    int blk = (t & 1) ? (dj ? 3 : 2) : (dj ? 1 : 0);   // i,f,g,o row blocks
    return blk * 32 + u;
}
// sigmoid-fold scale for a column: g-gate (odd tile, even col) keeps 1.0
__device__ __forceinline__ float gsc(int t, int dj) {
    return ((t & 1) && !dj) ? 1.0f : 0.5f;
}

__global__ void __launch_bounds__(128, 7) lstm_hmma_kernel(
    const float* __restrict__ hist,
    const float* __restrict__ Wih,
    const float* __restrict__ Whh,
    const float* __restrict__ bih,
    const float* __restrict__ bhh,
    const float* __restrict__ Wpred,
    const float* __restrict__ bpred,
    float* __restrict__ out)
{
    __shared__ __align__(16) __half Xhi[2][GSAMP][XH_STR];
    __shared__ __align__(16) __half Xx [2][GSAMP][XX_STR];

    const int tid  = threadIdx.x;
    const int lane = tid & 31;
    const int w    = tid >> 5;
    const int S0   = blockIdx.x * GSAMP;

    const int j    = lane & 3;
    const int nsub = lane >> 2;
    const int k0   = 2 * j;

    uint32_t Bh[4][2][2], Bx[4];          // Whh f16 (0.5-folded); x-chunk k8
    uint32_t Ph[2][2];                    // warp3 pred tile (decode)

#pragma unroll
    for (int t = 0; t < 4; t++) {
        int col = 32 * w + 8 * t + nsub;
        int pr  = prow(col);
        float sc = gsc(t, nsub & 1);
#pragma unroll
        for (int c = 0; c < 2; c++) {
            int kb = c * 16;
            Bh[t][c][0] = packh(sc * Whh[pr * 32 + kb + k0],
                                sc * Whh[pr * 32 + kb + k0 + 1]);
            Bh[t][c][1] = packh(sc * Whh[pr * 32 + kb + k0 + 8],
                                sc * Whh[pr * 32 + kb + k0 + 9]);
        }
        // x-chunk (k8): rows 0-3 = Wih cols, row 4 = bias (A row 4 = ones)
        float v0 = 0.0f, v1 = 0.0f;
        if (j == 0)      { v0 = sc * Wih[pr * 4 + 0]; v1 = sc * Wih[pr * 4 + 1]; }
        else if (j == 1) { v0 = sc * Wih[pr * 4 + 2]; v1 = sc * Wih[pr * 4 + 3]; }
        else if (j == 2) { v0 = sc * (bih[pr] + bhh[pr]); }
        Bx[t] = packh(v0, v1);
    }

    // ---------------- prime smem ----------------
    for (int i = tid; i < GSAMP * XH_STR; i += 128) {
        Xhi[0][i / XH_STR][i % XH_STR] = __float2half(0.0f);
    }
    if (tid < GSAMP) {
        const float4 x = ((const float4*)hist)[(size_t)(S0 + tid) * TSEQ];
        uint4 q;
        q.x = packh(x.x, x.y); q.y = packh(x.z, x.w);
        q.z = packh(1.0f, 0.0f); q.w = 0u;
        ((uint4*)&Xx[0][tid][0])[0] = q;
    }
    __syncthreads();

    // ldmatrix addressing
    const int mrow  = (lane & 7) + ((lane >> 3) & 1) * 8;
    const int mkoff = ((lane >> 4) & 1) * 16;      // bytes (Xhi x4 only)
    const uint32_t aXhi = s2u(&Xhi[0][0][0]);
    const uint32_t aXx  = s2u(&Xx[0][0][0]);
    const uint32_t PAR_H = GSAMP * XH_STR * 2;     // parity stride bytes
    const uint32_t PAR_X = GSAMP * XX_STR * 2;     // 256B

    const int r  = lane >> 2;                      // sample row (and r+8)
    const int u0 = 8 * w + j;                      // this lane's units
    const int u1 = u0 + 4;

    uint32_t cst2[2] = {0u, 0u};                   // c as f16x2 (rows r, r+8) per unit
    int p = 0;

    // =================== encoder: 200 steps ===================
    for (int step = 0; step < TSEQ; step++) {
        uint32_t Ah0[4], Ah1[4], Ax[2];
        {
            uint32_t ah = aXhi + (uint32_t)p * PAR_H + (uint32_t)mrow * (XH_STR * 2) + mkoff;
            uint32_t ax = aXx  + (uint32_t)p * PAR_X + (uint32_t)(lane & 15) * (XX_STR * 2);
            ldsm4(Ah0, ah); ldsm4(Ah1, ah + 32);
            ldsm2(Ax, ax);
        }

        // prefetch next encoder x while MMAs run
        float4 xn;
        const bool wantx = (step + 1 < TSEQ) && (w == 0) && (lane < GSAMP);
        if (wantx) xn = ((const float4*)hist)[(size_t)(S0 + lane) * TSEQ + step + 1];

        uint32_t dg[4][2];
#pragma unroll
        for (int t = 0; t < 4; t++) {
            dg[t][0] = 0u; dg[t][1] = 0u;
            mma16816h(dg[t], Ah0, Bh[t][0]);
            mma16816h(dg[t], Ah1, Bh[t][1]);
            mma1688h(dg[t], Ax, Bx[t]);
        }

        const uint32_t hbase = aXhi + (uint32_t)(p ^ 1) * PAR_H;
#pragma unroll
        for (int uu = 0; uu < 2; uu++) {
            uint32_t i2 = prmt(dg[2 * uu][0],     dg[2 * uu][1],     0x5410u);
            uint32_t f2 = prmt(dg[2 * uu][0],     dg[2 * uu][1],     0x7632u);
            uint32_t g2 = prmt(dg[2 * uu + 1][0], dg[2 * uu + 1][1], 0x5410u);
            uint32_t o2 = prmt(dg[2 * uu + 1][0], dg[2 * uu + 1][1], 0x7632u);
            uint32_t itg = mul2(sigm2f(i2), tanh2(g2));
            uint32_t cn2 = fma2h(sigm2f(f2), cst2[uu], itg);
            cst2[uu] = cn2;
            uint32_t h2 = mul2(sigm2f(o2), tanh2(cn2));
            int u = (uu == 0) ? u0 : u1;
            uint32_t alo = hbase + (uint32_t)(r * XH_STR + u) * 2u;
            sts_halves(h2, alo, alo + 8u * XH_STR * 2u);
        }

        if (wantx) {
            uint4 q;
            q.x = packh(xn.x, xn.y); q.y = packh(xn.z, xn.w);
            q.z = packh(1.0f, 0.0f); q.w = 0u;
            ((uint4*)&Xx[p ^ 1][lane][0])[0] = q;
        }

        __syncthreads();
        p ^= 1;
    }

    // =================== decode boundary: fused weights ===================
#pragma unroll
    for (int t = 0; t < 4; t++) {
        int col = 32 * w + 8 * t + nsub;
        int pr  = prow(col);
        float sc = gsc(t, nsub & 1);
#pragma unroll
        for (int c = 0; c < 2; c++) {
            int kb = c * 16;
            float wv[4];
#pragma unroll
            for (int q = 0; q < 4; q++) {
                int kk = kb + ((q < 2) ? k0 : k0 + 8) + (q & 1);
                float v = Whh[pr * 32 + kk];
#pragma unroll
                for (int d = 0; d < 4; d++)
                    v += Wih[pr * 4 + d] * Wpred[d * 32 + kk];
                wv[q] = sc * v;
            }
            Bh[t][c][0] = packh(wv[0], wv[1]);
            Bh[t][c][1] = packh(wv[2], wv[3]);
        }
        // Bx becomes the per-lane d-frag bias initializer: cols (2j, 2j+1)
        {
            int c0 = 32 * w + 8 * t + 2 * j;
            int pr0 = prow(c0), pr1 = prow(c0 + 1);
            float b0 = bih[pr0] + bhh[pr0];
            float b1 = bih[pr1] + bhh[pr1];
#pragma unroll
            for (int d = 0; d < 4; d++) {
                b0 += Wih[pr0 * 4 + d] * bpred[d];
                b1 += Wih[pr1 * 4 + d] * bpred[d];
            }
            Bx[t] = packh(gsc(t, 0) * b0, gsc(t, 1) * b1);
        }
    }
    // pred tile (warp3): cols = pred dims 0-3 (4-7 zero); bias via dp init
    {
        int d = nsub;
        bool ok = (d < 4);
#pragma unroll
        for (int c = 0; c < 2; c++) {
            int kb = c * 16;
            Ph[c][0] = packh(ok ? Wpred[d * 32 + kb + k0]     : 0.0f,
                             ok ? Wpred[d * 32 + kb + k0 + 1] : 0.0f);
            Ph[c][1] = packh(ok ? Wpred[d * 32 + kb + k0 + 8] : 0.0f,
                             ok ? Wpred[d * 32 + kb + k0 + 9] : 0.0f);
        }
    }
    const float bp0 = (j < 2) ? bpred[2 * j]     : 0.0f;
    const float bp1 = (j < 2) ? bpred[2 * j + 1] : 0.0f;

    // =================== decode: 50 steps ===================
    for (int ps = 0; ps < PSTEPS; ps++) {
        uint32_t Ah0[4], Ah1[4];
        {
            uint32_t ah = aXhi + (uint32_t)p * PAR_H + (uint32_t)mrow * (XH_STR * 2) + mkoff;
            ldsm4(Ah0, ah); ldsm4(Ah1, ah + 32);
        }

        uint32_t dg[4][2];
#pragma unroll
        for (int t = 0; t < 4; t++) {
            dg[t][0] = Bx[t]; dg[t][1] = Bx[t];    // bias-initialized accumulators
            mma16816h(dg[t], Ah0, Bh[t][0]);
            mma16816h(dg[t], Ah1, Bh[t][1]);
        }
        if (w == 3) {   // pred in f32 accum, bias-initialized
            float dp[4] = {bp0, bp1, bp0, bp1};
            mma16816(dp, Ah0, Ph[0]);
            mma16816(dp, Ah1, Ph[1]);
            if (j < 2) {
                float2* o0 = (float2*)(out + (size_t)(S0 + r)     * (PSTEPS * 4) + ps * 4 + k0);
                float2* o1 = (float2*)(out + (size_t)(S0 + r + 8) * (PSTEPS * 4) + ps * 4 + k0);
                *o0 = make_float2(dp[0], dp[1]);
                *o1 = make_float2(dp[2], dp[3]);
            }
        }

        const uint32_t hbase = aXhi + (uint32_t)(p ^ 1) * PAR_H;
#pragma unroll
        for (int uu = 0; uu < 2; uu++) {
            uint32_t i2 = prmt(dg[2 * uu][0],     dg[2 * uu][1],     0x5410u);
            uint32_t g2 = prmt(dg[2 * uu + 1][0], dg[2 * uu + 1][1], 0x5410u);
            uint32_t o2 = prmt(dg[2 * uu + 1][0], dg[2 * uu + 1][1], 0x7632u);
            uint32_t cn2 = mul2(sigm2f(i2), tanh2(g2));   // c resets each step
            uint32_t h2  = mul2(sigm2f(o2), tanh2(cn2));
            int u = (uu == 0) ? u0 : u1;
            uint32_t alo = hbase + (uint32_t)(r * XH_STR + u) * 2u;
            sts_halves(h2, alo, alo + 8u * XH_STR * 2u);
        }

        __syncthreads();
        p ^= 1;
    }
}

extern "C" void kernel_launch(void* const* d_in, const int* in_sizes, int n_in,
                              void* d_out, int out_size) {
    const float* hist  = (const float*)d_in[0];
    const float* Wih   = (const float*)d_in[1];
    const float* Whh   = (const float*)d_in[2];
    const float* bih   = (const float*)d_in[3];
    const float* bhh   = (const float*)d_in[4];
    const float* Wpred = (const float*)d_in[5];
    const float* bpred = (const float*)d_in[6];
    lstm_hmma_kernel<<<NCTA, 128>>>(hist, Wih, Whh, bih, bhh, Wpred, bpred,
                                    (float*)d_out);
}

// round 16
// speedup vs baseline: 1.3128x; 1.0448x over previous
#include <cuda_runtime.h>
#include <cuda_fp16.h>
#include <cstdint>

#define TSEQ 200
#define PSTEPS 50
#define BATCHN 32768
#define GSAMP 16
#define NCTA (BATCHN / GSAMP)   // 2048
#define XH_STR 40               // f16 elems per row (80B, 16B aligned, conflict-free ldsm)
#define XX_STR 8                // 16B rows (k8 x-chunk)
#define H05 0x38003800u         // (0.5, 0.5) f16x2

// ---------------- helpers ----------------
__device__ __forceinline__ uint32_t s2u(const void* p) {
    uint32_t a;
    asm("{ .reg .u64 t; cvta.to.shared.u64 t, %1; cvt.u32.u64 %0, t; }" : "=r"(a) : "l"(p));
    return a;
}
__device__ __forceinline__ uint32_t packh(float a, float b) {  // (f16(a), f16(b))
    uint32_t r;
    asm("{.reg .b16 x,y; cvt.rn.f16.f32 x, %1; cvt.rn.f16.f32 y, %2; mov.b32 %0, {x,y};}"
        : "=r"(r) : "f"(a), "f"(b));
    return r;
}
__device__ __forceinline__ uint32_t tanh2(uint32_t x) {
    uint32_t r; asm("tanh.approx.f16x2 %0, %1;" : "=r"(r) : "r"(x)); return r;
}
__device__ __forceinline__ uint32_t mul2(uint32_t a, uint32_t b) {
    uint32_t r; asm("mul.rn.f16x2 %0, %1, %2;" : "=r"(r) : "r"(a), "r"(b)); return r;
}
__device__ __forceinline__ uint32_t fma2h(uint32_t a, uint32_t b, uint32_t c) {
    uint32_t r; asm("fma.rn.f16x2 %0, %1, %2, %3;" : "=r"(r) : "r"(a), "r"(b), "r"(c)); return r;
}
// gates arrive pre-scaled by 0.5 (folded into weights): sigm = 0.5*tanh(g') + 0.5
__device__ __forceinline__ uint32_t sigm2f(uint32_t gpre) {
    return fma2h(H05, tanh2(gpre), H05);
}
// f16-accumulator gate MMAs
__device__ __forceinline__ void mma16816h(uint32_t* d, const uint32_t* a, const uint32_t* b) {
    asm volatile("mma.sync.aligned.m16n8k16.row.col.f16.f16.f16.f16 "
                 "{%0,%1}, {%2,%3,%4,%5}, {%6,%7}, {%0,%1};"
                 : "+r"(d[0]), "+r"(d[1])
                 : "r"(a[0]), "r"(a[1]), "r"(a[2]), "r"(a[3]), "r"(b[0]), "r"(b[1]));
}
__device__ __forceinline__ void mma1688h(uint32_t* d, const uint32_t* a, uint32_t b) {
    asm volatile("mma.sync.aligned.m16n8k8.row.col.f16.f16.f16.f16 "
                 "{%0,%1}, {%2,%3}, {%4}, {%0,%1};"
                 : "+r"(d[0]), "+r"(d[1])
                 : "r"(a[0]), "r"(a[1]), "r"(b));
}
// f32-accumulator MMA (pred output path only — error there is undamped)
__device__ __forceinline__ void mma16816(float* d, const uint32_t* a, const uint32_t* b) {
    asm volatile("mma.sync.aligned.m16n8k16.row.col.f32.f16.f16.f32 "
                 "{%0,%1,%2,%3}, {%4,%5,%6,%7}, {%8,%9}, {%0,%1,%2,%3};"
                 : "+f"(d[0]), "+f"(d[1]), "+f"(d[2]), "+f"(d[3])
                 : "r"(a[0]), "r"(a[1]), "r"(a[2]), "r"(a[3]), "r"(b[0]), "r"(b[1]));
}
__device__ __forceinline__ void ldsm4(uint32_t* r, uint32_t addr) {
    asm volatile("ldmatrix.sync.aligned.m8n8.x4.shared.b16 {%0,%1,%2,%3}, [%4];"
                 : "=r"(r[0]), "=r"(r[1]), "=r"(r[2]), "=r"(r[3]) : "r"(addr));
}
__device__ __forceinline__ void ldsm2(uint32_t* r, uint32_t addr) {
    asm volatile("ldmatrix.sync.aligned.m8n8.x2.shared.b16 {%0,%1}, [%2];"
                 : "=r"(r[0]), "=r"(r[1]) : "r"(addr));
}
__device__ __forceinline__ void sts32(uint32_t v, uint32_t a) {
    asm volatile("st.shared.b32 [%0], %1;" :: "r"(a), "r"(v));
}

// Gate-major column map: tile t = gate t (PyTorch order i,f,g,o), col c = unit
// 8w+c.  Lane j's accumulator dg[t][rr] is directly the f16x2
// (gate_t of units 8w+2j, 8w+2j+1) at row rr — no PRMT, STS.32 h-commit.
// gate row in weight matrices: pr = t*32 + 8*w + c.
// sigmoid fold: gates i,f,o scaled by 0.5; g (t==2) unscaled.

__global__ void __launch_bounds__(128, 7) lstm_hmma_kernel(
    const float* __restrict__ hist,
    const float* __restrict__ Wih,
    const float* __restrict__ Whh,
    const float* __restrict__ bih,
    const float* __restrict__ bhh,
    const float* __restrict__ Wpred,
    const float* __restrict__ bpred,
    float* __restrict__ out)
{
    __shared__ __align__(16) __half Xhi[2][GSAMP][XH_STR];
    __shared__ __align__(16) __half Xx [2][GSAMP][XX_STR];

    const int tid  = threadIdx.x;
    const int lane = tid & 31;
    const int w    = tid >> 5;
    const int S0   = blockIdx.x * GSAMP;

    const int j    = lane & 3;
    const int nsub = lane >> 2;
    const int k0   = 2 * j;

    uint32_t Bh[4][2][2], Bx[4];          // Whh f16 (0.5-folded); x-chunk k8
    uint32_t Ph[2][2];                    // warp3 pred tile (decode)

#pragma unroll
    for (int t = 0; t < 4; t++) {
        int pr = t * 32 + 8 * w + nsub;   // gate t, unit 8w+nsub
        float sc = (t == 2) ? 1.0f : 0.5f;
#pragma unroll
        for (int c = 0; c < 2; c++) {
            int kb = c * 16;
            Bh[t][c][0] = packh(sc * Whh[pr * 32 + kb + k0],
                                sc * Whh[pr * 32 + kb + k0 + 1]);
            Bh[t][c][1] = packh(sc * Whh[pr * 32 + kb + k0 + 8],
                                sc * Whh[pr * 32 + kb + k0 + 9]);
        }
        // x-chunk (k8): rows 0-3 = Wih cols, row 4 = bias (A row 4 = ones)
        float v0 = 0.0f, v1 = 0.0f;
        if (j == 0)      { v0 = sc * Wih[pr * 4 + 0]; v1 = sc * Wih[pr * 4 + 1]; }
        else if (j == 1) { v0 = sc * Wih[pr * 4 + 2]; v1 = sc * Wih[pr * 4 + 3]; }
        else if (j == 2) { v0 = sc * (bih[pr] + bhh[pr]); }
        Bx[t] = packh(v0, v1);
    }

    // ---------------- prime smem ----------------
    for (int i = tid; i < GSAMP * XH_STR; i += 128) {
        Xhi[0][i / XH_STR][i % XH_STR] = __float2half(0.0f);
    }
    if (tid < GSAMP) {
        const float4 x = ((const float4*)hist)[(size_t)(S0 + tid) * TSEQ];
        uint4 q;
        q.x = packh(x.x, x.y); q.y = packh(x.z, x.w);
        q.z = packh(1.0f, 0.0f); q.w = 0u;
        ((uint4*)&Xx[0][tid][0])[0] = q;
    }
    __syncthreads();

    // ldmatrix addressing
    const int mrow  = (lane & 7) + ((lane >> 3) & 1) * 8;
    const int mkoff = ((lane >> 4) & 1) * 16;      // bytes (Xhi x4 only)
    const uint32_t aXhi = s2u(&Xhi[0][0][0]);
    const uint32_t aXx  = s2u(&Xx[0][0][0]);
    const uint32_t PAR_H = GSAMP * XH_STR * 2;     // parity stride bytes
    const uint32_t PAR_X = GSAMP * XX_STR * 2;     // 256B

    const int r  = lane >> 2;                      // sample row (and r+8)
    const int u0 = 8 * w + 2 * j;                  // this lane's unit pair (u0, u0+1)

    uint32_t cst2[2] = {0u, 0u};                   // c as f16x2(u0,u0+1), rows r / r+8
    int p = 0;

    // =================== encoder: 200 steps ===================
    for (int step = 0; step < TSEQ; step++) {
        uint32_t Ah0[4], Ah1[4], Ax[2];
        {
            uint32_t ah = aXhi + (uint32_t)p * PAR_H + (uint32_t)mrow * (XH_STR * 2) + mkoff;
            uint32_t ax = aXx  + (uint32_t)p * PAR_X + (uint32_t)(lane & 15) * (XX_STR * 2);
            ldsm4(Ah0, ah); ldsm4(Ah1, ah + 32);
            ldsm2(Ax, ax);
        }

        // prefetch next encoder x while MMAs run
        float4 xn;
        const bool wantx = (step + 1 < TSEQ) && (w == 0) && (lane < GSAMP);
        if (wantx) xn = ((const float4*)hist)[(size_t)(S0 + lane) * TSEQ + step + 1];

        uint32_t dg[4][2];
#pragma unroll
        for (int t = 0; t < 4; t++) {
            dg[t][0] = 0u; dg[t][1] = 0u;
            mma16816h(dg[t], Ah0, Bh[t][0]);
            mma16816h(dg[t], Ah1, Bh[t][1]);
            mma1688h(dg[t], Ax, Bx[t]);
        }

        // ---- epilogue: accumulators ARE (unit-pair) f16x2 — no repack ----
        const uint32_t hbase = aXhi + (uint32_t)(p ^ 1) * PAR_H;
#pragma unroll
        for (int rr = 0; rr < 2; rr++) {
            uint32_t itg = mul2(sigm2f(dg[0][rr]), tanh2(dg[2][rr]));
            uint32_t cn2 = fma2h(sigm2f(dg[1][rr]), cst2[rr], itg);
            cst2[rr] = cn2;
            uint32_t h2 = mul2(sigm2f(dg[3][rr]), tanh2(cn2));
            int row = r + rr * 8;
            sts32(h2, hbase + (uint32_t)(row * XH_STR + u0) * 2u);
        }

        if (wantx) {
            uint4 q;
            q.x = packh(xn.x, xn.y); q.y = packh(xn.z, xn.w);
            q.z = packh(1.0f, 0.0f); q.w = 0u;
            ((uint4*)&Xx[p ^ 1][lane][0])[0] = q;
        }

        __syncthreads();
        p ^= 1;
    }

    // =================== decode boundary: fused weights ===================
#pragma unroll
    for (int t = 0; t < 4; t++) {
        int pr = t * 32 + 8 * w + nsub;
        float sc = (t == 2) ? 1.0f : 0.5f;
#pragma unroll
        for (int c = 0; c < 2; c++) {
            int kb = c * 16;
            float wv[4];
#pragma unroll
            for (int q = 0; q < 4; q++) {
                int kk = kb + ((q < 2) ? k0 : k0 + 8) + (q & 1);
                float v = Whh[pr * 32 + kk];
#pragma unroll
                for (int d = 0; d < 4; d++)
                    v += Wih[pr * 4 + d] * Wpred[d * 32 + kk];
                wv[q] = sc * v;
            }
            Bh[t][c][0] = packh(wv[0], wv[1]);
            Bh[t][c][1] = packh(wv[2], wv[3]);
        }
        // Bx becomes the per-lane d-frag bias initializer: unit pair (u0, u0+1)
        {
            int pr0 = t * 32 + 8 * w + 2 * j;
            int pr1 = pr0 + 1;
            float b0 = bih[pr0] + bhh[pr0];
            float b1 = bih[pr1] + bhh[pr1];
#pragma unroll
            for (int d = 0; d < 4; d++) {
                b0 += Wih[pr0 * 4 + d] * bpred[d];
                b1 += Wih[pr1 * 4 + d] * bpred[d];
            }
            Bx[t] = packh(sc * b0, sc * b1);
        }
    }
    // pred tile (warp3): cols = pred dims 0-3 (4-7 zero); bias via dp init
    {
        int d = nsub;
        bool ok = (d < 4);
#pragma unroll
        for (int c = 0; c < 2; c++) {
            int kb = c * 16;
            Ph[c][0] = packh(ok ? Wpred[d * 32 + kb + k0]     : 0.0f,
                             ok ? Wpred[d * 32 + kb + k0 + 1] : 0.0f);
            Ph[c][1] = packh(ok ? Wpred[d * 32 + kb + k0 + 8] : 0.0f,
                             ok ? Wpred[d * 32 + kb + k0 + 9] : 0.0f);
        }
    }
    const float bp0 = (j < 2) ? bpred[2 * j]     : 0.0f;
    const float bp1 = (j < 2) ? bpred[2 * j + 1] : 0.0f;

    // =================== decode: 50 steps (f gate dead: c resets) ===========
    for (int ps = 0; ps < PSTEPS; ps++) {
        uint32_t Ah0[4], Ah1[4];
        {
            uint32_t ah = aXhi + (uint32_t)p * PAR_H + (uint32_t)mrow * (XH_STR * 2) + mkoff;
            ldsm4(Ah0, ah); ldsm4(Ah1, ah + 32);
        }

        uint32_t dgi[2], dgg[2], dgo[2];
        dgi[0] = Bx[0]; dgi[1] = Bx[0];
        dgg[0] = Bx[2]; dgg[1] = Bx[2];
        dgo[0] = Bx[3]; dgo[1] = Bx[3];
        mma16816h(dgi, Ah0, Bh[0][0]); mma16816h(dgi, Ah1, Bh[0][1]);
        mma16816h(dgg, Ah0, Bh[2][0]); mma16816h(dgg, Ah1, Bh[2][1]);
        mma16816h(dgo, Ah0, Bh[3][0]); mma16816h(dgo, Ah1, Bh[3][1]);

        if (w == 3) {   // pred in f32 accum, bias-initialized
            float dp[4] = {bp0, bp1, bp0, bp1};
            mma16816(dp, Ah0, Ph[0]);
            mma16816(dp, Ah1, Ph[1]);
            if (j < 2) {
                float2* o0 = (float2*)(out + (size_t)(S0 + r)     * (PSTEPS * 4) + ps * 4 + k0);
                float2* o1 = (float2*)(out + (size_t)(S0 + r + 8) * (PSTEPS * 4) + ps * 4 + k0);
                *o0 = make_float2(dp[0], dp[1]);
                *o1 = make_float2(dp[2], dp[3]);
            }
        }

        const uint32_t hbase = aXhi + (uint32_t)(p ^ 1) * PAR_H;
#pragma unroll
        for (int rr = 0; rr < 2; rr++) {
            uint32_t cn2 = mul2(sigm2f(dgi[rr]), tanh2(dgg[rr]));   // c resets
            uint32_t h2  = mul2(sigm2f(dgo[rr]), tanh2(cn2));
            int row = r + rr * 8;
            sts32(h2, hbase + (uint32_t)(row * XH_STR + u0) * 2u);
        }

        __syncthreads();
        p ^= 1;
    }
}

extern "C" void kernel_launch(void* const* d_in, const int* in_sizes, int n_in,
                              void* d_out, int out_size) {
    const float* hist  = (const float*)d_in[0];
    const float* Wih   = (const float*)d_in[1];
    const float* Whh   = (const float*)d_in[2];
    const float* bih   = (const float*)d_in[3];
    const float* bhh   = (const float*)d_in[4];
    const float* Wpred = (const float*)d_in[5];
    const float* bpred = (const float*)d_in[6];
    lstm_hmma_kernel<<<NCTA, 128>>>(hist, Wih, Whh, bih, bhh, Wpred, bpred,
                                    (float*)d_out);
}